// round 10
// baseline (speedup 1.0000x reference)
#include <cuda_runtime.h>
#include <cstdint>
#include <cstddef>

#define BATCH 256
#define TSEQ  512
#define IDIM  64
#define HDIM  512
#define ODIM  512
#define JCTAS   8            // j-partition: CTA r owns j in [64r, 64r+64)
#define BGROUPS 16           // batch groups of 16 rows (2 streams x 8)
#define STEP_THREADS 128

typedef unsigned long long ull;

// ---- scratch (static device allocations only) ----
__device__ float  g_xp[(size_t)TSEQ * BATCH * HDIM];    // [t][b][h], 256 MiB
// hidden state, transposed + splatted: g_ht2[par][j*BATCH + b] = {v,v}
__device__ float2 g_ht2[2][(size_t)HDIM * BATCH];       // 2 MiB
__device__ float  g_hlast[(size_t)BATCH * HDIM];        // final h, [b][j]
// flags[stream][(g*8 + r)*32], one 128B line each
__device__ unsigned g_flags[2][BGROUPS * JCTAS * 32];

// ---- packed f32x2 helpers ----
__device__ __forceinline__ ull pk2(float lo, float hi) {
    ull r; asm("mov.b64 %0, {%1,%2};" : "=l"(r) : "f"(lo), "f"(hi)); return r;
}
__device__ __forceinline__ float2 upk2(ull v) {
    float2 r; asm("mov.b64 {%0,%1}, %2;" : "=f"(r.x), "=f"(r.y) : "l"(v)); return r;
}
__device__ __forceinline__ ull fma2(ull a, ull b, ull c) {
    ull d; asm("fma.rn.f32x2 %0, %1, %2, %3;" : "=l"(d) : "l"(a), "l"(b), "l"(c)); return d;
}

// ---- smem layout ----
#define WS_BYTES  131072                  // Whh slice [512][64] floats
#define HBUF_B    32768                   // one stream's staged h: [512 k][8 b] float2
#define SMEM_TOTAL (WS_BYTES + 2 * HBUF_B)    // 192 KB

// ============================================================================
__global__ void init_flags_kernel() {
    for (int i = threadIdx.x; i < 2 * BGROUPS * JCTAS * 32; i += blockDim.x)
        ((unsigned*)g_flags)[i] = 0u;
}

// ============================================================================
// Kernel A: xp[t][b][:] = x[b][t][:] @ Whx + bh.  8 rows (same b) per CTA.
// ============================================================================
__global__ void __launch_bounds__(128) xproj_kernel(
    const float* __restrict__ x, const float* __restrict__ Whx,
    const float* __restrict__ bh)
{
    __shared__ float xs[8][IDIM];
    int row0 = blockIdx.x * 8;
    int b = row0 >> 9, t0 = row0 & (TSEQ - 1);
    int tid = threadIdx.x;
    for (int i = tid; i < 8 * IDIM; i += 128)
        xs[i >> 6][i & 63] = x[(size_t)(row0 + (i >> 6)) * IDIM + (i & 63)];
    __syncthreads();

    int j0 = tid * 4;
    ull a[8][2] = {};
    #pragma unroll 4
    for (int k = 0; k < IDIM; k++) {
        float4 w = *reinterpret_cast<const float4*>(Whx + (size_t)k * HDIM + j0);
        ull w01 = pk2(w.x, w.y), w23 = pk2(w.z, w.w);
        #pragma unroll
        for (int r = 0; r < 8; r++) {
            float xv = xs[r][k];
            ull x2 = pk2(xv, xv);
            a[r][0] = fma2(w01, x2, a[r][0]);
            a[r][1] = fma2(w23, x2, a[r][1]);
        }
    }
    float4 bv = *reinterpret_cast<const float4*>(bh + j0);
    #pragma unroll
    for (int r = 0; r < 8; r++) {
        float2 p0 = upk2(a[r][0]), p1 = upk2(a[r][1]);
        float4 o;
        o.x = p0.x + bv.x; o.y = p0.y + bv.y;
        o.z = p1.x + bv.z; o.w = p1.y + bv.w;
        *reinterpret_cast<float4*>(
            g_xp + ((size_t)(t0 + r) * BATCH + b) * HDIM + j0) = o;
    }
}

// ============================================================================
// Kernel B: persistent recurrence, TWO interleaved batch streams per CTA.
// Grid (8 j, 16 b) = 128 CTAs x 128 thr (4 warps -> all SMSPs), single wave.
// CTA (r,g): j in [64r,64r+64); stream s covers b in [16g+8s, 16g+8s+8).
// Half-step pipeline: while stream S computes, stream S^1's flags are polled
// and its whole-K h tile (32KB, pre-splatted) streams in via one cp.async
// group, hiding publish->detect->staging latency.
// Thread tile 4j x 1b: per kl = LDS.128(W) + LDS.64(h-splat) + 2 FFMA2,
// zero register packs in the mainloop.
// ============================================================================
__global__ void __launch_bounds__(STEP_THREADS, 1) rnn_persistent(
    const float* __restrict__ Whh)
{
    extern __shared__ char sm[];
    float* ws = reinterpret_cast<float*>(sm);                    // [512][64]
    char*  hbuf = sm + WS_BYTES;                                 // 2 x 32KB
    uint32_t hbuf_u32 = (uint32_t)__cvta_generic_to_shared(hbuf);

    const int r = blockIdx.x;          // 0..7  (j slice)
    const int g = blockIdx.y;          // 0..15 (batch group)
    const int tid = threadIdx.x;
    const int jg = tid >> 3;           // 0..15 -> j quad
    const int bl = tid & 7;            // 0..7  -> b lane within stream
    const int jl0 = jg * 4;
    const int j0g = r * 64 + jl0;

    // ---- load Whh slice (once) ----
    for (int i = tid; i < 512 * 16; i += STEP_THREADS) {
        int k = i >> 4, q = (i & 15) * 4;
        *reinterpret_cast<float4*>(ws + (size_t)k * 64 + q) =
            *reinterpret_cast<const float4*>(Whh + (size_t)k * HDIM + r * 64 + q);
    }
    __syncthreads();

    unsigned* myflag[2] = { &g_flags[0][(g * JCTAS + r) * 32],
                            &g_flags[1][(g * JCTAS + r) * 32] };

    // ---- poll all 8 producers of stream s for step t (8 lanes, 1 flag each,
    //      bounded spin with nanosleep backoff) ----
    auto poll = [&](int s, unsigned tv) {
        if (tid < 8) {
            unsigned* f = &g_flags[s][(g * JCTAS + tid) * 32];
            unsigned v;
            for (;;) {
                asm volatile("ld.acquire.gpu.global.u32 %0, [%1];"
                             : "=r"(v) : "l"(f) : "memory");
                if (v >= tv) break;
                __nanosleep(32);
            }
        }
        __syncthreads();
    };
    // ---- stage stream s's h (step t-1 output) into hbuf[s]; 1 group ----
    auto issue = [&](int s, int t) {
        const float2* src = g_ht2[(t - 1) & 1] + g * 16 + s * 8;
        uint32_t dst = hbuf_u32 + s * HBUF_B;
        // 2048 segs of 16B: e = p*128 + tid; k = e>>2, sg = e&3
        #pragma unroll
        for (int p = 0; p < 16; p++) {
            int e = p * 128 + tid;
            int k = e >> 2, sg = e & 3;
            asm volatile("cp.async.cg.shared.global [%0], [%1], 16;"
                         :: "r"(dst + (uint32_t)(k * 64 + sg * 16)),
                            "l"(src + (size_t)k * BATCH + sg * 2) : "memory");
        }
        asm volatile("cp.async.commit_group;" ::: "memory");
    };
    // ---- compute + epilogue + publish for stream s, step t ----
    auto do_step = [&](int s, int t, bool mainloop) {
        const int bg2 = g * 16 + s * 8 + bl;          // global b
        const float* xpt = g_xp + (size_t)t * BATCH * HDIM;
        float4 xv = *reinterpret_cast<const float4*>(xpt + (size_t)bg2 * HDIM + j0g);
        ull a01 = 0ull, a23 = 0ull;
        if (mainloop) {
            const float* wk = ws + jl0;
            const char*  hk = hbuf + s * HBUF_B + bl * 8;
            #pragma unroll 8
            for (int kl = 0; kl < 512; kl++) {
                ulonglong2 w2 = *reinterpret_cast<const ulonglong2*>(wk + (size_t)kl * 64);
                ull hs = *reinterpret_cast<const ull*>(hk + (size_t)kl * 64);
                a01 = fma2(w2.x, hs, a01);
                a23 = fma2(w2.y, hs, a23);
            }
        }
        float2 p0 = upk2(a01), p1 = upk2(a23);
        float o0 = tanhf(xv.x + p0.x), o1 = tanhf(xv.y + p0.y);
        float o2 = tanhf(xv.z + p1.x), o3 = tanhf(xv.w + p1.y);
        float2* hout = g_ht2[t & 1];
        hout[(size_t)(j0g + 0) * BATCH + bg2] = make_float2(o0, o0);
        hout[(size_t)(j0g + 1) * BATCH + bg2] = make_float2(o1, o1);
        hout[(size_t)(j0g + 2) * BATCH + bg2] = make_float2(o2, o2);
        hout[(size_t)(j0g + 3) * BATCH + bg2] = make_float2(o3, o3);
        if (t == TSEQ - 1)
            *reinterpret_cast<float4*>(g_hlast + (size_t)bg2 * HDIM + j0g) =
                make_float4(o0, o1, o2, o3);
        __syncthreads();                              // stores + hbuf reads done
        if (tid == 0)
            asm volatile("st.release.gpu.global.u32 [%0], %1;"
                         :: "l"(myflag[s]), "r"((unsigned)(t + 1)) : "memory");
    };

    // ---- prologue: step 0 for both streams (h0 = 0 -> tanh(xp)) ----
    do_step(0, 0, false);
    do_step(1, 0, false);

    // ---- pipelined half-step loop: 1022 half-steps ----
    poll(0, 1); issue(0, 1);
    for (int i = 0; i < 2 * (TSEQ - 1); i++) {
        int s = i & 1;
        int t = (i >> 1) + 1;
        if (i < 2 * (TSEQ - 1) - 1) {
            int ns = s ^ 1;
            int nt = ((i + 1) >> 1) + 1;
            poll(ns, (unsigned)nt);
            issue(ns, nt);
            asm volatile("cp.async.wait_group 1;" ::: "memory");
        } else {
            asm volatile("cp.async.wait_group 0;" ::: "memory");
        }
        __syncthreads();
        do_step(s, t, true);
    }
}

// ============================================================================
// Kernel C: out[b][:] = softmax(h_last[b][:] @ Wph + bo).
// ============================================================================
__global__ void __launch_bounds__(128) out_softmax_kernel(
    const float* __restrict__ Wph, const float* __restrict__ bo,
    float* __restrict__ out)
{
    __shared__ float hsr[HDIM];
    __shared__ float red[128];
    int b = blockIdx.x, tid = threadIdx.x;
    for (int k = tid; k < HDIM; k += 128)
        hsr[k] = g_hlast[(size_t)b * HDIM + k];
    __syncthreads();

    int j0 = tid * 4;
    ull a0 = 0ull, a1 = 0ull;
    #pragma unroll 8
    for (int k = 0; k < HDIM; k++) {
        float4 w = *reinterpret_cast<const float4*>(Wph + (size_t)k * ODIM + j0);
        ull hv = pk2(hsr[k], hsr[k]);
        a0 = fma2(pk2(w.x, w.y), hv, a0);
        a1 = fma2(pk2(w.z, w.w), hv, a1);
    }
    float4 bv = *reinterpret_cast<const float4*>(bo + j0);
    float2 p0 = upk2(a0), p1 = upk2(a1);
    float4 v;
    v.x = p0.x + bv.x; v.y = p0.y + bv.y;
    v.z = p1.x + bv.z; v.w = p1.y + bv.w;

    float m = fmaxf(fmaxf(v.x, v.y), fmaxf(v.z, v.w));
    red[tid] = m;
    __syncthreads();
    for (int s = 64; s > 0; s >>= 1) {
        if (tid < s) red[tid] = fmaxf(red[tid], red[tid + s]);
        __syncthreads();
    }
    m = red[0];
    __syncthreads();

    v.x = expf(v.x - m); v.y = expf(v.y - m);
    v.z = expf(v.z - m); v.w = expf(v.w - m);
    red[tid] = v.x + v.y + v.z + v.w;
    __syncthreads();
    for (int s = 64; s > 0; s >>= 1) {
        if (tid < s) red[tid] += red[tid + s];
        __syncthreads();
    }
    float inv = 1.0f / red[0];
    v.x *= inv; v.y *= inv; v.z *= inv; v.w *= inv;
    *reinterpret_cast<float4*>(out + (size_t)b * ODIM + j0) = v;
}

// ============================================================================
extern "C" void kernel_launch(void* const* d_in, const int* in_sizes, int n_in,
                              void* d_out, int out_size)
{
    const float* x   = (const float*)d_in[0];
    const float* Whx = (const float*)d_in[1];
    const float* Whh = (const float*)d_in[2];
    const float* bh  = (const float*)d_in[3];
    const float* Wph = (const float*)d_in[4];
    const float* bo  = (const float*)d_in[5];
    float* out = (float*)d_out;

    cudaFuncSetAttribute(rnn_persistent,
                         cudaFuncAttributeMaxDynamicSharedMemorySize, SMEM_TOTAL);

    init_flags_kernel<<<1, 256>>>();
    xproj_kernel<<<BATCH * TSEQ / 8, 128>>>(x, Whx, bh);
    rnn_persistent<<<dim3(JCTAS, BGROUPS), STEP_THREADS, SMEM_TOTAL>>>(Whh);
    out_softmax_kernel<<<BATCH, 128>>>(Wph, bo, out);
}

// round 11
// speedup vs baseline: 1.2671x; 1.2671x over previous
#include <cuda_runtime.h>
#include <cstdint>
#include <cstddef>

#define BATCH 256
#define TSEQ  512
#define IDIM  64
#define HDIM  512
#define ODIM  512
#define GRID_STEP 128        // persistent CTAs (<=148 SMs, 1 CTA/SM, single wave)
#define STEP_THREADS 128

typedef unsigned long long ull;

// ---- scratch (static device allocations only) ----
__device__ float  g_xp[(size_t)TSEQ * BATCH * HDIM];   // [t][b][h], 256 MiB
// hidden state, transposed + splatted: g_ht[buf][h*BATCH + b] = {v, v}
__device__ float2 g_ht[2][(size_t)HDIM * BATCH];       // 2 MiB
__device__ unsigned g_bar;                             // grid barrier (self-resetting)

// ---- packed f32x2 helpers ----
__device__ __forceinline__ ull pk2(float lo, float hi) {
    ull r; asm("mov.b64 %0, {%1,%2};" : "=l"(r) : "f"(lo), "f"(hi)); return r;
}
__device__ __forceinline__ float2 upk2(ull v) {
    float2 r; asm("mov.b64 {%0,%1}, %2;" : "=f"(r.x), "=f"(r.y) : "l"(v)); return r;
}
__device__ __forceinline__ ull fma2(ull a, ull b, ull c) {
    ull d; asm("fma.rn.f32x2 %0, %1, %2, %3;" : "=l"(d) : "l"(a), "l"(b), "l"(c)); return d;
}

// ---- grid barrier (R3-identical: busy spin, single counter) ----
__device__ __forceinline__ void bar_wait(unsigned target) {
    if (threadIdx.x == 0) {
        unsigned v;
        do {
            asm volatile("ld.acquire.gpu.global.u32 %0, [%1];"
                         : "=r"(v) : "l"(&g_bar) : "memory");
        } while (v < target);
    }
    __syncthreads();
}
__device__ __forceinline__ void bar_arrive(unsigned total) {
    __syncthreads();
    if (threadIdx.x == 0) {
        unsigned old;
        asm volatile("atom.release.gpu.global.add.u32 %0, [%1], %2;"
                     : "=r"(old) : "l"(&g_bar), "r"(1u) : "memory");
        if (old == total - 1u)
            asm volatile("st.relaxed.gpu.global.u32 [%0], %1;"
                         :: "l"(&g_bar), "r"(0u) : "memory");
    }
}

// ============================================================================
// pad kernel: no-op, used only to position rnn_persistent at global launch #6
// so ncu (-s 5 -c 1) finally captures it.
// ============================================================================
__global__ void pad_kernel() {}

// ============================================================================
// Kernel A: xp[t][b][:] = x[b][t][:] @ Whx + bh.  4 rows (same b) per CTA.
// (R3-identical)
// ============================================================================
__global__ void __launch_bounds__(128) xproj_kernel(
    const float* __restrict__ x, const float* __restrict__ Whx,
    const float* __restrict__ bh)
{
    __shared__ float xs[4][IDIM];
    int row0 = blockIdx.x * 4;
    int b = row0 >> 9, t0 = row0 & (TSEQ - 1);
    int tid = threadIdx.x;
    for (int i = tid; i < 4 * IDIM; i += 128)
        xs[i >> 6][i & 63] = x[(size_t)(row0 + (i >> 6)) * IDIM + (i & 63)];
    __syncthreads();

    int j0 = tid * 4;
    ull a[4][2] = {};
    #pragma unroll 4
    for (int k = 0; k < IDIM; k++) {
        float4 w = *reinterpret_cast<const float4*>(Whx + (size_t)k * HDIM + j0);
        ull w01 = pk2(w.x, w.y), w23 = pk2(w.z, w.w);
        #pragma unroll
        for (int r = 0; r < 4; r++) {
            float xv = xs[r][k];
            ull x2 = pk2(xv, xv);
            a[r][0] = fma2(w01, x2, a[r][0]);
            a[r][1] = fma2(w23, x2, a[r][1]);
        }
    }
    float4 bv = *reinterpret_cast<const float4*>(bh + j0);
    #pragma unroll
    for (int r = 0; r < 4; r++) {
        float2 p0 = upk2(a[r][0]), p1 = upk2(a[r][1]);
        float4 o;
        o.x = p0.x + bv.x; o.y = p0.y + bv.y;
        o.z = p1.x + bv.z; o.w = p1.y + bv.w;
        *reinterpret_cast<float4*>(
            g_xp + ((size_t)(t0 + r) * BATCH + b) * HDIM + j0) = o;
    }
}

// ============================================================================
// Kernel B: persistent recurrence — R3 structure verbatim, inner loop patched
// to zero-pack form (W and splatted h consumed as ulonglong2 pairs):
// per kl per thread: LDS.128 W + LDS.128 h-splats + 4 FFMA2 = 6 instr.
// Grid (16 j, 8 b) = 128 CTAs x 128 threads; CTA tile 32j x 32b;
// Whh slice [512][32] SMEM-resident (64 KB); h staged per step via
// double-buffered cp.async.cg in 4 chunks of [128 k][32 b] float2 (32 KB).
// ============================================================================
__global__ void __launch_bounds__(STEP_THREADS, 1) rnn_persistent(
    const float* __restrict__ Whh)
{
    extern __shared__ char smraw[];
    float* ws = reinterpret_cast<float*>(smraw);          // [512][32]  64 KB
    char*  hsb = smraw + 65536;                           // 2 x 32 KB

    const int tid  = threadIdx.x;
    const int lane = tid & 31, wrp = tid >> 5;
    const int jg = lane & 7, bg = lane >> 3;
    const int j0c = blockIdx.x * 32;
    const int b0c = blockIdx.y * 32;
    const int j0 = j0c + jg * 4;
    const int bl = wrp * 8 + bg * 2;        // local b (even)
    const int b0 = b0c + bl;

    // ---- load Whh slice into SMEM (once) ----
    for (int i = tid; i < 512 * 8; i += STEP_THREADS) {
        int k = i >> 3, c = i & 7;
        *reinterpret_cast<float4*>(ws + k * 32 + c * 4) =
            *reinterpret_cast<const float4*>(Whh + (size_t)k * HDIM + j0c + c * 4);
    }
    __syncthreads();

    // staging thread mapping: 16 segments of 16B per k-row; 8 k-rows per pass
    const int seg  = tid & 15;
    const int krow = tid >> 4;              // 0..7

    for (int t = 0; t < TSEQ; t++) {
        const float* xpt = g_xp + (size_t)t * BATCH * HDIM;
        float4 xv0 = *reinterpret_cast<const float4*>(xpt + (size_t)b0 * HDIM + j0);
        float4 xv1 = *reinterpret_cast<const float4*>(xpt + (size_t)(b0 + 1) * HDIM + j0);
        ull a00 = 0ull, a10 = 0ull, a01 = 0ull, a11 = 0ull;

        if (t > 0) {
            bar_wait((unsigned)t * GRID_STEP);
            const float2* hin = g_ht[(t - 1) & 1];

            // issue chunk 0
            {
                const float2* src = hin + (size_t)krow * BATCH + b0c + seg * 2;
                uint32_t dst = (uint32_t)__cvta_generic_to_shared(
                    hsb + ((size_t)krow * 32 + seg * 2) * 8);
                #pragma unroll
                for (int p = 0; p < 16; p++)
                    asm volatile("cp.async.cg.shared.global [%0], [%1], 16;"
                                 :: "r"(dst + p * 2048), "l"(src + p * 2048) : "memory");
                asm volatile("cp.async.commit_group;" ::: "memory");
            }

            #pragma unroll
            for (int c = 0; c < 4; c++) {
                asm volatile("cp.async.wait_group 0;" ::: "memory");
                __syncthreads();
                if (c < 3) {
                    const float2* src = hin + (size_t)((c + 1) * 128 + krow) * BATCH
                                        + b0c + seg * 2;
                    uint32_t dst = (uint32_t)__cvta_generic_to_shared(
                        hsb + ((size_t)((c + 1) & 1)) * 32768
                            + ((size_t)krow * 32 + seg * 2) * 8);
                    #pragma unroll
                    for (int p = 0; p < 16; p++)
                        asm volatile("cp.async.cg.shared.global [%0], [%1], 16;"
                                     :: "r"(dst + p * 2048), "l"(src + p * 2048) : "memory");
                    asm volatile("cp.async.commit_group;" ::: "memory");
                }
                // compute chunk c from buffer c&1 — zero-pack inner loop
                const float* wk = ws + (c * 128) * 32 + jg * 4;
                const char*  hk = hsb + (c & 1) * 32768 + bl * 8;
                #pragma unroll 8
                for (int kl = 0; kl < 128; kl++) {
                    ulonglong2 w2 = *reinterpret_cast<const ulonglong2*>(wk + (size_t)kl * 32);
                    ulonglong2 h2 = *reinterpret_cast<const ulonglong2*>(hk + (size_t)kl * 256);
                    // w2.x={w0,w1} w2.y={w2,w3}; h2.x={hb0,hb0} h2.y={hb1,hb1}
                    a00 = fma2(w2.x, h2.x, a00);
                    a10 = fma2(w2.y, h2.x, a10);
                    a01 = fma2(w2.x, h2.y, a01);
                    a11 = fma2(w2.y, h2.y, a11);
                }
            }
        }

        // ---- epilogue: add xp, tanh, store splatted-transposed h ----
        float2* hout = g_ht[t & 1];
        float2 p0 = upk2(a00), p1 = upk2(a10), p2 = upk2(a01), p3 = upk2(a11);
        float o0[4] = { tanhf(xv0.x + p0.x), tanhf(xv0.y + p0.y),
                        tanhf(xv0.z + p1.x), tanhf(xv0.w + p1.y) };
        float o1[4] = { tanhf(xv1.x + p2.x), tanhf(xv1.y + p2.y),
                        tanhf(xv1.z + p3.x), tanhf(xv1.w + p3.y) };
        #pragma unroll
        for (int jj = 0; jj < 4; jj++) {
            hout[(size_t)(j0 + jj) * BATCH + b0]     = make_float2(o0[jj], o0[jj]);
            hout[(size_t)(j0 + jj) * BATCH + b0 + 1] = make_float2(o1[jj], o1[jj]);
        }
        bar_arrive((unsigned)TSEQ * GRID_STEP);
    }
}

// ============================================================================
// Kernel C: out[b][:] = softmax(h_last @ Wph + bo). h_last = g_ht[1]
// (t=511 -> buffer 1), splatted-transposed: read .x at [k*BATCH + b].
// (R3-identical)
// ============================================================================
__global__ void __launch_bounds__(128) out_softmax_kernel(
    const float* __restrict__ Wph, const float* __restrict__ bo,
    float* __restrict__ out)
{
    __shared__ float hsr[HDIM];
    __shared__ float red[128];
    int b = blockIdx.x, tid = threadIdx.x;
    for (int k = tid; k < HDIM; k += 128)
        hsr[k] = g_ht[1][(size_t)k * BATCH + b].x;
    __syncthreads();

    int j0 = tid * 4;
    ull a0 = 0ull, a1 = 0ull;
    #pragma unroll 8
    for (int k = 0; k < HDIM; k++) {
        float4 w = *reinterpret_cast<const float4*>(Wph + (size_t)k * ODIM + j0);
        ull hv = pk2(hsr[k], hsr[k]);
        a0 = fma2(pk2(w.x, w.y), hv, a0);
        a1 = fma2(pk2(w.z, w.w), hv, a1);
    }
    float4 bv = *reinterpret_cast<const float4*>(bo + j0);
    float2 p0 = upk2(a0), p1 = upk2(a1);
    float4 v;
    v.x = p0.x + bv.x; v.y = p0.y + bv.y;
    v.z = p1.x + bv.z; v.w = p1.y + bv.w;

    float m = fmaxf(fmaxf(v.x, v.y), fmaxf(v.z, v.w));
    red[tid] = m;
    __syncthreads();
    for (int s = 64; s > 0; s >>= 1) {
        if (tid < s) red[tid] = fmaxf(red[tid], red[tid + s]);
        __syncthreads();
    }
    m = red[0];
    __syncthreads();

    v.x = expf(v.x - m); v.y = expf(v.y - m);
    v.z = expf(v.z - m); v.w = expf(v.w - m);
    red[tid] = v.x + v.y + v.z + v.w;
    __syncthreads();
    for (int s = 64; s > 0; s >>= 1) {
        if (tid < s) red[tid] += red[tid + s];
        __syncthreads();
    }
    float inv = 1.0f / red[0];
    v.x *= inv; v.y *= inv; v.z *= inv; v.w *= inv;
    *reinterpret_cast<float4*>(out + (size_t)b * ODIM + j0) = v;
}

// ============================================================================
// Launch order: 4 pads + xproj + rnn + soft = 7 launches/call.
// Global launch #6 (ncu -s 5 -c 1) = rnn_persistent of the first call.
// ============================================================================
extern "C" void kernel_launch(void* const* d_in, const int* in_sizes, int n_in,
                              void* d_out, int out_size)
{
    const float* x   = (const float*)d_in[0];
    const float* Whx = (const float*)d_in[1];
    const float* Whh = (const float*)d_in[2];
    const float* bh  = (const float*)d_in[3];
    const float* Wph = (const float*)d_in[4];
    const float* bo  = (const float*)d_in[5];
    float* out = (float*)d_out;

    cudaFuncSetAttribute(rnn_persistent,
                         cudaFuncAttributeMaxDynamicSharedMemorySize, 131072);

    pad_kernel<<<1, 32>>>();
    pad_kernel<<<1, 32>>>();
    pad_kernel<<<1, 32>>>();
    pad_kernel<<<1, 32>>>();
    xproj_kernel<<<BATCH * TSEQ / 4, 128>>>(x, Whx, bh);
    rnn_persistent<<<dim3(16, 8), STEP_THREADS, 131072>>>(Whh);
    out_softmax_kernel<<<BATCH, 128>>>(Wph, bo, out);
}